// round 15
// baseline (speedup 1.0000x reference)
#include <cuda_runtime.h>
#include <cuda_fp16.h>
#include <cstdint>

// Geometry
#define DIN    1024
#define DOUT   1024
#define MTOT   32768            // B*S
#define K2     512              // compacted K (2:4 column-global mask)
#define BM     128
#define BN     128
#define BK     64
#define KCH    8                // K2/BK
#define MT     (MTOT / BM)      // 256
#define NT     (DOUT / BN)      // 8
#define THREADS 128
#define STAGES 3

// fp16 fragment-major compact operands.
// A tile (mt,kc) = 16KB: frag fi = mtl(8)*4 + ks(4); 512B frag, lane*16B.
// B tile (nt,kc) = 16KB: frag fj = p(8)*4 + ks(4); pair p covers ntiles 2p,2p+1.
#define A_STAGE_BYTES (BM * BK * 2)    // 16384
#define B_STAGE_BYTES (BN * BK * 2)    // 16384
__device__ __align__(128) unsigned char g_xc[(size_t)MT * KCH * A_STAGE_BYTES]; // 32 MB
__device__ __align__(128) unsigned char g_wc[(size_t)NT * KCH * B_STAGE_BYTES]; //  1 MB

// smem staging stride (words): 36 -> conflict-free phase-2 gather
#define HSTRIDE 36

// ------------------------------------------------------------------ helpers
__device__ __forceinline__ uint32_t smem_u32(const void* p) {
    uint32_t a;
    asm("{ .reg .u64 t; cvta.to.shared.u64 t, %1; cvt.u32.u64 %0, t; }"
        : "=r"(a) : "l"(p));
    return a;
}
__device__ __forceinline__ uint32_t h2bits(float a, float b) {
    __half2 h = __floats2half2_rn(a, b);
    return *reinterpret_cast<uint32_t*>(&h);
}
__device__ __forceinline__ void cp16(uint32_t dst, const void* src) {
    asm volatile("cp.async.cg.shared.global [%0], [%1], 16;"
                 :: "r"(dst), "l"(src) : "memory");
}
__device__ __forceinline__ void cp_commit() {
    asm volatile("cp.async.commit_group;" ::: "memory");
}
template <int N>
__device__ __forceinline__ void cp_wait() {
    asm volatile("cp.async.wait_group %0;" :: "n"(N) : "memory");
}
__device__ __forceinline__ void lds128(uint32_t (&r)[4], uint32_t addr) {
    asm volatile("ld.shared.v4.u32 {%0,%1,%2,%3}, [%4];"
                 : "=r"(r[0]), "=r"(r[1]), "=r"(r[2]), "=r"(r[3]) : "r"(addr));
}
__device__ __forceinline__ void mma_f16(float (&d)[4], const uint32_t (&a)[4],
                                        uint32_t b0, uint32_t b1) {
    asm volatile(
        "mma.sync.aligned.m16n8k16.row.col.f32.f16.f16.f32 "
        "{%0,%1,%2,%3}, {%4,%5,%6,%7}, {%8,%9}, {%0,%1,%2,%3};"
        : "+f"(d[0]), "+f"(d[1]), "+f"(d[2]), "+f"(d[3])
        : "r"(a[0]), "r"(a[1]), "r"(a[2]), "r"(a[3]), "r"(b0), "r"(b1));
}

// ------------------------------------------------------------------ prepass
// Two-tile pipelined compact. Each block handles one (tile, kc-pair):
// kc0 = 2q, kc1 = 2q+1. Double-buffered hsw; kc1's first load batch is
// hoisted BEFORE kc0's phase-2 stores so the DRAM read stream never drains.
// Blocks [0, MT*KCH/2) do x -> A-frag order; rest do w -> B-frag order.
__global__ void __launch_bounds__(256) compact_kernel(const float4* __restrict__ x4,
                                                      const float4* __restrict__ w4,
                                                      const float4* __restrict__ mask4) {
    __shared__ uint32_t hsw[2][128 * HSTRIDE];
    __shared__ int s_j0[2][32], s_j1[2][32];

    const int b = blockIdx.x;
    const bool isx = (b < MT * KCH / 2);
    const int bb = isx ? b : (b - MT * KCH / 2);
    const int tile = bb >> 2;
    const int kc0 = (bb & 3) * 2;           // kc pair (kc0, kc0+1)
    const float4* __restrict__ src = isx ? x4 : w4;
    const int tid = threadIdx.x;

    // selectors for both kc in the pair
    if (tid < 64) {
        int q = tid >> 5, t = tid & 31;
        float4 m = mask4[(kc0 + q) * 32 + t];
        float mv[4] = {m.x, m.y, m.z, m.w};
        int j0 = -1, j1 = -1;
        #pragma unroll
        for (int j = 3; j >= 0; j--)
            if (mv[j] != 0.0f) { j1 = j0; j0 = j; }
        s_j0[q][t] = j0;
        s_j1[q][t] = j1;
    }
    __syncthreads();

    // -- phase 1 for kc0 -> hsw[0] (R8 two-batch structure) --
    #pragma unroll
    for (int h = 0; h < 2; h++) {
        float4 f[8];
        #pragma unroll
        for (int j = 0; j < 8; j++) {
            int idx = tid + 256 * (h * 8 + j);
            int row = idx >> 5, gl = idx & 31;
            f[j] = __ldg(&src[(size_t)(tile * 128 + row) * (DIN / 4) + kc0 * 32 + gl]);
        }
        #pragma unroll
        for (int j = 0; j < 8; j++) {
            int idx = tid + 256 * (h * 8 + j);
            int row = idx >> 5, gl = idx & 31;
            int j0 = s_j0[0][gl], j1 = s_j1[0][gl];
            float v0 = (j0 == 0) ? f[j].x : (j0 == 1) ? f[j].y : (j0 == 2) ? f[j].z : f[j].w;
            float v1 = (j1 == 0) ? f[j].x : (j1 == 1) ? f[j].y : (j1 == 2) ? f[j].z : f[j].w;
            if (j0 < 0) v0 = 0.0f;
            if (j1 < 0) v1 = 0.0f;
            hsw[0][row * HSTRIDE + gl] = h2bits(v0, v1);
        }
    }
    __syncthreads();

    // -- hoist kc1 batch-0 loads (8 float4 in flight across kc0 phase 2) --
    float4 g[8];
    #pragma unroll
    for (int j = 0; j < 8; j++) {
        int idx = tid + 256 * j;
        int row = idx >> 5, gl = idx & 31;
        g[j] = __ldg(&src[(size_t)(tile * 128 + row) * (DIN / 4) + (kc0 + 1) * 32 + gl]);
    }

    // -- phase 2 for kc0 (gather from hsw[0], store to gmem) --
    auto phase2 = [&](const uint32_t* hb, int kc) {
        if (isx) {
            unsigned char* dst = g_xc + ((size_t)(tile * KCH + kc)) * A_STAGE_BYTES;
            #pragma unroll
            for (int j = 0; j < 4; j++) {
                int o = tid + 256 * j;
                int l = o & 31, fi = o >> 5;
                int ks = fi & 3, mtl = fi >> 2;
                int r = mtl * 16 + (l >> 2);
                int wb = ks * 8 + (l & 3);
                uint4 v;
                v.x = hb[r * HSTRIDE + wb];
                v.y = hb[(r + 8) * HSTRIDE + wb];
                v.z = hb[r * HSTRIDE + wb + 4];
                v.w = hb[(r + 8) * HSTRIDE + wb + 4];
                *reinterpret_cast<uint4*>(dst + o * 16) = v;
            }
        } else {
            unsigned char* dst = g_wc + ((size_t)(tile * KCH + kc)) * B_STAGE_BYTES;
            #pragma unroll
            for (int j = 0; j < 4; j++) {
                int o = tid + 256 * j;
                int l = o & 31, fj = o >> 5;
                int ks = fj & 3, p = fj >> 2;
                int n = p * 16 + (l >> 2);
                int pr = ks * 8 + (l & 3);
                uint4 v;
                v.x = hb[n * HSTRIDE + pr];
                v.y = hb[n * HSTRIDE + pr + 4];
                v.z = hb[(n + 8) * HSTRIDE + pr];
                v.w = hb[(n + 8) * HSTRIDE + pr + 4];
                *reinterpret_cast<uint4*>(dst + o * 16) = v;
            }
        }
    };
    phase2(hsw[0], kc0);

    // -- finish phase 1 for kc1 -> hsw[1]: convert g, then batch 1 --
    #pragma unroll
    for (int j = 0; j < 8; j++) {
        int idx = tid + 256 * j;
        int row = idx >> 5, gl = idx & 31;
        int j0 = s_j0[1][gl], j1 = s_j1[1][gl];
        float v0 = (j0 == 0) ? g[j].x : (j0 == 1) ? g[j].y : (j0 == 2) ? g[j].z : g[j].w;
        float v1 = (j1 == 0) ? g[j].x : (j1 == 1) ? g[j].y : (j1 == 2) ? g[j].z : g[j].w;
        if (j0 < 0) v0 = 0.0f;
        if (j1 < 0) v1 = 0.0f;
        hsw[1][row * HSTRIDE + gl] = h2bits(v0, v1);
    }
    {
        float4 f[8];
        #pragma unroll
        for (int j = 0; j < 8; j++) {
            int idx = tid + 256 * (8 + j);
            int row = idx >> 5, gl = idx & 31;
            f[j] = __ldg(&src[(size_t)(tile * 128 + row) * (DIN / 4) + (kc0 + 1) * 32 + gl]);
        }
        #pragma unroll
        for (int j = 0; j < 8; j++) {
            int idx = tid + 256 * (8 + j);
            int row = idx >> 5, gl = idx & 31;
            int j0 = s_j0[1][gl], j1 = s_j1[1][gl];
            float v0 = (j0 == 0) ? f[j].x : (j0 == 1) ? f[j].y : (j0 == 2) ? f[j].z : f[j].w;
            float v1 = (j1 == 0) ? f[j].x : (j1 == 1) ? f[j].y : (j1 == 2) ? f[j].z : f[j].w;
            if (j0 < 0) v0 = 0.0f;
            if (j1 < 0) v1 = 0.0f;
            hsw[1][row * HSTRIDE + gl] = h2bits(v0, v1);
        }
    }
    __syncthreads();

    // -- phase 2 for kc1 --
    phase2(hsw[1], kc0 + 1);
}

// ------------------------------------------------------------------ GEMM
// R8 configuration (DO NOT TOUCH): 3 stages x (16KB A + 16KB B) = 96KB,
// 2 CTAs/SM, in-register fragment double buffering, one __syncthreads/chunk.
#define SMEM_BYTES (STAGES * (A_STAGE_BYTES + B_STAGE_BYTES))   // 98304

__global__ void __launch_bounds__(THREADS, 2) gemm_kernel(float* __restrict__ out) {
    extern __shared__ char smem[];
    const uint32_t sA0 = smem_u32(smem);
    const uint32_t sB0 = sA0 + STAGES * A_STAGE_BYTES;

    const int tid = threadIdx.x;
    const int wid = tid >> 5, lid = tid & 31;
    const int nt = blockIdx.x, mt = blockIdx.y;
    const int wm = wid & 1;         // 2 m-warps (64 rows)
    const int wn = wid >> 1;        // 2 n-warps (64 cols = 4 pairs)

    const unsigned char* gA = g_xc + ((size_t)mt * KCH) * A_STAGE_BYTES;
    const unsigned char* gB = g_wc + ((size_t)nt * KCH) * B_STAGE_BYTES;

    auto load_stage = [&](int s, int c) {
        uint32_t dA = sA0 + s * A_STAGE_BYTES + tid * 16;
        const unsigned char* srcA = gA + (size_t)c * A_STAGE_BYTES + tid * 16;
        #pragma unroll
        for (int j = 0; j < 8; j++) cp16(dA + j * 2048, srcA + j * 2048);
        uint32_t dB = sB0 + s * B_STAGE_BYTES + tid * 16;
        const unsigned char* srcB = gB + (size_t)c * B_STAGE_BYTES + tid * 16;
        #pragma unroll
        for (int j = 0; j < 8; j++) cp16(dB + j * 2048, srcB + j * 2048);
    };

    float acc[4][8][4];
    #pragma unroll
    for (int i = 0; i < 4; i++)
        #pragma unroll
        for (int j = 0; j < 8; j++)
            #pragma unroll
            for (int v = 0; v < 4; v++) acc[i][j][v] = 0.0f;

    uint32_t ab[2][4][4], bb[2][4][4];
    auto ldfrags = [&](int buf, int s, int ks) {
        const uint32_t aB = sA0 + s * A_STAGE_BYTES + ((wm * 4) * 4 + ks) * 512 + lid * 16;
        #pragma unroll
        for (int i = 0; i < 4; i++) lds128(ab[buf][i], aB + i * 2048);
        const uint32_t bB = sB0 + s * B_STAGE_BYTES + ((wn * 4) * 4 + ks) * 512 + lid * 16;
        #pragma unroll
        for (int p = 0; p < 4; p++) lds128(bb[buf][p], bB + p * 2048);
    };
    auto domma = [&](int buf) {
        #pragma unroll
        for (int i = 0; i < 4; i++)
            #pragma unroll
            for (int p = 0; p < 4; p++) {
                mma_f16(acc[i][2 * p],     ab[buf][i], bb[buf][p][0], bb[buf][p][1]);
                mma_f16(acc[i][2 * p + 1], ab[buf][i], bb[buf][p][2], bb[buf][p][3]);
            }
    };

    // prologue: fill stages 0,1; load ks0 frags of chunk 0
    load_stage(0, 0); cp_commit();
    load_stage(1, 1); cp_commit();
    cp_wait<1>();
    __syncthreads();
    ldfrags(0, 0, 0);

    int s = 0;
    for (int c = 0; c < KCH; c++) {
        const int snext = (s == STAGES - 1) ? 0 : s + 1;
        const int sload = (snext == STAGES - 1) ? 0 : snext + 1;
        if (c + 2 < KCH) load_stage(sload, c + 2);
        cp_commit();

        ldfrags(1, s, 1); domma(0);     // ks0 compute, ks1 prefetch
        ldfrags(0, s, 2); domma(1);     // ks1
        ldfrags(1, s, 3); domma(0);     // ks2
        cp_wait<1>();                   // chunk c+1 resident (c+2 may pend)
        __syncthreads();                // stage s fully read CTA-wide
        if (c + 1 < KCH) ldfrags(0, snext, 0);
        domma(1);                       // ks3
        s = snext;
    }

    // epilogue: d frag (r,2c): d0,d1 @ row r; d2,d3 @ row r+8
    const int rowW = mt * BM + wm * 64 + (lid >> 2);
    const int colW = nt * BN + wn * 64 + (lid & 3) * 2;
    #pragma unroll
    for (int i = 0; i < 4; i++) {
        const size_t r0 = (size_t)(rowW + i * 16) * DOUT;
        const size_t r1 = r0 + (size_t)8 * DOUT;
        #pragma unroll
        for (int j = 0; j < 8; j++) {
            const int cc = colW + j * 8;
            *reinterpret_cast<float2*>(out + r0 + cc) =
                make_float2(acc[i][j][0], acc[i][j][1]);
            *reinterpret_cast<float2*>(out + r1 + cc) =
                make_float2(acc[i][j][2], acc[i][j][3]);
        }
    }
}

// ------------------------------------------------------------------ launch
extern "C" void kernel_launch(void* const* d_in, const int* in_sizes, int n_in,
                              void* d_out, int out_size) {
    const float* x    = (const float*)d_in[0];
    const float* w    = (const float*)d_in[1];
    const float* mask = (const float*)d_in[2];
    float* out        = (float*)d_out;

    cudaFuncSetAttribute(gemm_kernel,
                         cudaFuncAttributeMaxDynamicSharedMemorySize, SMEM_BYTES);

    compact_kernel<<<(MT * KCH + NT * KCH) / 2, 256>>>((const float4*)x,
                                                       (const float4*)w,
                                                       (const float4*)mask);
    gemm_kernel<<<dim3(NT, MT), THREADS, SMEM_BYTES>>>(out);
}

// round 16
// speedup vs baseline: 1.0923x; 1.0923x over previous
#include <cuda_runtime.h>
#include <cuda_fp16.h>
#include <cstdint>

// Geometry
#define DIN    1024
#define DOUT   1024
#define MTOT   32768            // B*S
#define K2     512              // compacted K (2:4 column-global mask)
#define BM     128
#define BN     128
#define BK     64
#define KCH    8                // K2/BK
#define MT     (MTOT / BM)      // 256
#define NT     (DOUT / BN)      // 8
#define THREADS 128
#define STAGES 3

// fp16 fragment-major compact operands.
// A tile (mt,kc) = 16KB: frag fi = mtl(8)*4 + ks(4); 512B frag, lane*16B.
// B tile (nt,kc) = 16KB: frag fj = p(8)*4 + ks(4); pair p covers ntiles 2p,2p+1.
#define A_STAGE_BYTES (BM * BK * 2)    // 16384
#define B_STAGE_BYTES (BN * BK * 2)    // 16384
__device__ __align__(128) unsigned char g_xc[(size_t)MT * KCH * A_STAGE_BYTES]; // 32 MB
__device__ __align__(128) unsigned char g_wc[(size_t)NT * KCH * B_STAGE_BYTES]; //  1 MB

// smem staging stride (words): 36 -> conflict-free phase-2 gather
#define HSTRIDE 36

// ------------------------------------------------------------------ helpers
__device__ __forceinline__ uint32_t smem_u32(const void* p) {
    uint32_t a;
    asm("{ .reg .u64 t; cvta.to.shared.u64 t, %1; cvt.u32.u64 %0, t; }"
        : "=r"(a) : "l"(p));
    return a;
}
__device__ __forceinline__ uint32_t h2bits(float a, float b) {
    __half2 h = __floats2half2_rn(a, b);
    return *reinterpret_cast<uint32_t*>(&h);
}
__device__ __forceinline__ void cp16(uint32_t dst, const void* src) {
    asm volatile("cp.async.cg.shared.global [%0], [%1], 16;"
                 :: "r"(dst), "l"(src) : "memory");
}
__device__ __forceinline__ void cp_commit() {
    asm volatile("cp.async.commit_group;" ::: "memory");
}
template <int N>
__device__ __forceinline__ void cp_wait() {
    asm volatile("cp.async.wait_group %0;" :: "n"(N) : "memory");
}
__device__ __forceinline__ void lds128(uint32_t (&r)[4], uint32_t addr) {
    asm volatile("ld.shared.v4.u32 {%0,%1,%2,%3}, [%4];"
                 : "=r"(r[0]), "=r"(r[1]), "=r"(r[2]), "=r"(r[3]) : "r"(addr));
}
__device__ __forceinline__ void mma_f16(float (&d)[4], const uint32_t (&a)[4],
                                        uint32_t b0, uint32_t b1) {
    asm volatile(
        "mma.sync.aligned.m16n8k16.row.col.f32.f16.f16.f32 "
        "{%0,%1,%2,%3}, {%4,%5,%6,%7}, {%8,%9}, {%0,%1,%2,%3};"
        : "+f"(d[0]), "+f"(d[1]), "+f"(d[2]), "+f"(d[3])
        : "r"(a[0]), "r"(a[1]), "r"(a[2]), "r"(a[3]), "r"(b0), "r"(b1));
}
// streaming (evict-first) float4 load / float2 store
__device__ __forceinline__ float4 ldcs4(const float4* p) {
    float4 v;
    asm volatile("ld.global.cs.v4.f32 {%0,%1,%2,%3}, [%4];"
                 : "=f"(v.x), "=f"(v.y), "=f"(v.z), "=f"(v.w) : "l"(p));
    return v;
}
__device__ __forceinline__ void stcs2(float2* p, float a, float b) {
    asm volatile("st.global.cs.v2.f32 [%0], {%1,%2};"
                 :: "l"(p), "f"(a), "f"(b) : "memory");
}

// ------------------------------------------------------------------ prepass
// One kernel: blocks [0, MT*KCH) compact x into A-frag order; blocks
// [MT*KCH, MT*KCH + NT*KCH) compact w into B-frag order. Mask is column-global.
__global__ void __launch_bounds__(256) compact_kernel(const float4* __restrict__ x4,
                                                      const float4* __restrict__ w4,
                                                      const float4* __restrict__ mask4) {
    __shared__ uint32_t hsw[128 * HSTRIDE];
    __shared__ int s_j0[32], s_j1[32];

    const int b = blockIdx.x;
    const bool isx = (b < MT * KCH);
    const int bb = isx ? b : (b - MT * KCH);
    const int kc = bb & (KCH - 1);
    const int tile = bb >> 3;
    const float4* __restrict__ src = isx ? x4 : w4;
    const int tid = threadIdx.x;

    if (tid < 32) {
        float4 m = mask4[kc * 32 + tid];
        float mv[4] = {m.x, m.y, m.z, m.w};
        int j0 = -1, j1 = -1;
        #pragma unroll
        for (int j = 3; j >= 0; j--)
            if (mv[j] != 0.0f) { j1 = j0; j0 = j; }
        s_j0[tid] = j0;
        s_j1[tid] = j1;
    }
    __syncthreads();

    // phase 1: coalesced streaming float4 reads (read-once), batched x8 for MLP
    #pragma unroll
    for (int h = 0; h < 2; h++) {
        float4 f[8];
        #pragma unroll
        for (int j = 0; j < 8; j++) {
            int idx = tid + 256 * (h * 8 + j);
            int row = idx >> 5, gl = idx & 31;
            f[j] = ldcs4(&src[(size_t)(tile * 128 + row) * (DIN / 4) + kc * 32 + gl]);
        }
        #pragma unroll
        for (int j = 0; j < 8; j++) {
            int idx = tid + 256 * (h * 8 + j);
            int row = idx >> 5, gl = idx & 31;
            int j0 = s_j0[gl], j1 = s_j1[gl];
            float v0 = (j0 == 0) ? f[j].x : (j0 == 1) ? f[j].y : (j0 == 2) ? f[j].z : f[j].w;
            float v1 = (j1 == 0) ? f[j].x : (j1 == 1) ? f[j].y : (j1 == 2) ? f[j].z : f[j].w;
            if (j0 < 0) v0 = 0.0f;
            if (j1 < 0) v1 = 0.0f;
            hsw[row * HSTRIDE + gl] = h2bits(v0, v1);
        }
    }
    __syncthreads();

    if (isx) {
        unsigned char* dst = g_xc + ((size_t)(tile * KCH + kc)) * A_STAGE_BYTES;
        #pragma unroll
        for (int j = 0; j < 4; j++) {
            int o = tid + 256 * j;
            int l = o & 31, fi = o >> 5;
            int ks = fi & 3, mtl = fi >> 2;
            int r = mtl * 16 + (l >> 2);
            int wb = ks * 8 + (l & 3);
            uint4 v;
            v.x = hsw[r * HSTRIDE + wb];
            v.y = hsw[(r + 8) * HSTRIDE + wb];
            v.z = hsw[r * HSTRIDE + wb + 4];
            v.w = hsw[(r + 8) * HSTRIDE + wb + 4];
            *reinterpret_cast<uint4*>(dst + o * 16) = v;
        }
    } else {
        unsigned char* dst = g_wc + ((size_t)(tile * KCH + kc)) * B_STAGE_BYTES;
        #pragma unroll
        for (int j = 0; j < 4; j++) {
            int o = tid + 256 * j;
            int l = o & 31, fj = o >> 5;
            int ks = fj & 3, p = fj >> 2;
            int n = p * 16 + (l >> 2);
            int pr = ks * 8 + (l & 3);
            uint4 v;
            v.x = hsw[n * HSTRIDE + pr];
            v.y = hsw[n * HSTRIDE + pr + 4];
            v.z = hsw[(n + 8) * HSTRIDE + pr];
            v.w = hsw[(n + 8) * HSTRIDE + pr + 4];
            *reinterpret_cast<uint4*>(dst + o * 16) = v;
        }
    }
}

// ------------------------------------------------------------------ GEMM
// R8 configuration (DO NOT TOUCH): 3 stages x (16KB A + 16KB B) = 96KB,
// 2 CTAs/SM, in-register fragment double buffering, one __syncthreads/chunk.
#define SMEM_BYTES (STAGES * (A_STAGE_BYTES + B_STAGE_BYTES))   // 98304

__global__ void __launch_bounds__(THREADS, 2) gemm_kernel(float* __restrict__ out) {
    extern __shared__ char smem[];
    const uint32_t sA0 = smem_u32(smem);
    const uint32_t sB0 = sA0 + STAGES * A_STAGE_BYTES;

    const int tid = threadIdx.x;
    const int wid = tid >> 5, lid = tid & 31;
    const int nt = blockIdx.x, mt = blockIdx.y;
    const int wm = wid & 1;         // 2 m-warps (64 rows)
    const int wn = wid >> 1;        // 2 n-warps (64 cols = 4 pairs)

    const unsigned char* gA = g_xc + ((size_t)mt * KCH) * A_STAGE_BYTES;
    const unsigned char* gB = g_wc + ((size_t)nt * KCH) * B_STAGE_BYTES;

    auto load_stage = [&](int s, int c) {
        uint32_t dA = sA0 + s * A_STAGE_BYTES + tid * 16;
        const unsigned char* srcA = gA + (size_t)c * A_STAGE_BYTES + tid * 16;
        #pragma unroll
        for (int j = 0; j < 8; j++) cp16(dA + j * 2048, srcA + j * 2048);
        uint32_t dB = sB0 + s * B_STAGE_BYTES + tid * 16;
        const unsigned char* srcB = gB + (size_t)c * B_STAGE_BYTES + tid * 16;
        #pragma unroll
        for (int j = 0; j < 8; j++) cp16(dB + j * 2048, srcB + j * 2048);
    };

    float acc[4][8][4];
    #pragma unroll
    for (int i = 0; i < 4; i++)
        #pragma unroll
        for (int j = 0; j < 8; j++)
            #pragma unroll
            for (int v = 0; v < 4; v++) acc[i][j][v] = 0.0f;

    uint32_t ab[2][4][4], bb[2][4][4];
    auto ldfrags = [&](int buf, int s, int ks) {
        const uint32_t aB = sA0 + s * A_STAGE_BYTES + ((wm * 4) * 4 + ks) * 512 + lid * 16;
        #pragma unroll
        for (int i = 0; i < 4; i++) lds128(ab[buf][i], aB + i * 2048);
        const uint32_t bB = sB0 + s * B_STAGE_BYTES + ((wn * 4) * 4 + ks) * 512 + lid * 16;
        #pragma unroll
        for (int p = 0; p < 4; p++) lds128(bb[buf][p], bB + p * 2048);
    };
    auto domma = [&](int buf) {
        #pragma unroll
        for (int i = 0; i < 4; i++)
            #pragma unroll
            for (int p = 0; p < 4; p++) {
                mma_f16(acc[i][2 * p],     ab[buf][i], bb[buf][p][0], bb[buf][p][1]);
                mma_f16(acc[i][2 * p + 1], ab[buf][i], bb[buf][p][2], bb[buf][p][3]);
            }
    };

    // prologue: fill stages 0,1; load ks0 frags of chunk 0
    load_stage(0, 0); cp_commit();
    load_stage(1, 1); cp_commit();
    cp_wait<1>();
    __syncthreads();
    ldfrags(0, 0, 0);

    int s = 0;
    for (int c = 0; c < KCH; c++) {
        const int snext = (s == STAGES - 1) ? 0 : s + 1;
        const int sload = (snext == STAGES - 1) ? 0 : snext + 1;
        if (c + 2 < KCH) load_stage(sload, c + 2);
        cp_commit();

        ldfrags(1, s, 1); domma(0);     // ks0 compute, ks1 prefetch
        ldfrags(0, s, 2); domma(1);     // ks1
        ldfrags(1, s, 3); domma(0);     // ks2
        cp_wait<1>();                   // chunk c+1 resident (c+2 may pend)
        __syncthreads();                // stage s fully read CTA-wide
        if (c + 1 < KCH) ldfrags(0, snext, 0);
        domma(1);                       // ks3
        s = snext;
    }

    // epilogue: streaming stores (output is never re-read; keep L2 for g_xc)
    const int rowW = mt * BM + wm * 64 + (lid >> 2);
    const int colW = nt * BN + wn * 64 + (lid & 3) * 2;
    #pragma unroll
    for (int i = 0; i < 4; i++) {
        const size_t r0 = (size_t)(rowW + i * 16) * DOUT;
        const size_t r1 = r0 + (size_t)8 * DOUT;
        #pragma unroll
        for (int j = 0; j < 8; j++) {
            const int cc = colW + j * 8;
            stcs2(reinterpret_cast<float2*>(out + r0 + cc), acc[i][j][0], acc[i][j][1]);
            stcs2(reinterpret_cast<float2*>(out + r1 + cc), acc[i][j][2], acc[i][j][3]);
        }
    }
}

// ------------------------------------------------------------------ launch
extern "C" void kernel_launch(void* const* d_in, const int* in_sizes, int n_in,
                              void* d_out, int out_size) {
    const float* x    = (const float*)d_in[0];
    const float* w    = (const float*)d_in[1];
    const float* mask = (const float*)d_in[2];
    float* out        = (float*)d_out;

    cudaFuncSetAttribute(gemm_kernel,
                         cudaFuncAttributeMaxDynamicSharedMemorySize, SMEM_BYTES);

    compact_kernel<<<MT * KCH + NT * KCH, 256>>>((const float4*)x, (const float4*)w,
                                                 (const float4*)mask);
    gemm_kernel<<<dim3(NT, MT), THREADS, SMEM_BYTES>>>(out);
}

// round 17
// speedup vs baseline: 1.0952x; 1.0026x over previous
#include <cuda_runtime.h>
#include <cuda_fp16.h>
#include <cstdint>

// Geometry
#define DIN    1024
#define DOUT   1024
#define MTOT   32768            // B*S
#define K2     512              // compacted K (2:4 column-global mask)
#define BM     128
#define BN     128
#define BK     64
#define KCH    8                // K2/BK
#define MT     (MTOT / BM)      // 256
#define NT     (DOUT / BN)      // 8
#define THREADS 128
#define STAGES 3

// fp16 fragment-major compact operands.
// A tile (mt,kc) = 16KB: frag fi = mtl(8)*4 + ks(4); 512B frag, lane*16B.
// B tile (nt,kc) = 16KB: frag fj = p(8)*4 + ks(4); pair p covers ntiles 2p,2p+1.
#define A_STAGE_BYTES (BM * BK * 2)    // 16384
#define B_STAGE_BYTES (BN * BK * 2)    // 16384
__device__ __align__(128) unsigned char g_xc[(size_t)MT * KCH * A_STAGE_BYTES]; // 32 MB
__device__ __align__(128) unsigned char g_wc[(size_t)NT * KCH * B_STAGE_BYTES]; //  1 MB

// smem staging stride (words): 36 -> conflict-free phase-2 gather
#define HSTRIDE 36

// ------------------------------------------------------------------ helpers
__device__ __forceinline__ uint32_t smem_u32(const void* p) {
    uint32_t a;
    asm("{ .reg .u64 t; cvta.to.shared.u64 t, %1; cvt.u32.u64 %0, t; }"
        : "=r"(a) : "l"(p));
    return a;
}
__device__ __forceinline__ uint32_t h2bits(float a, float b) {
    __half2 h = __floats2half2_rn(a, b);
    return *reinterpret_cast<uint32_t*>(&h);
}
__device__ __forceinline__ void cp16(uint32_t dst, const void* src) {
    asm volatile("cp.async.cg.shared.global [%0], [%1], 16;"
                 :: "r"(dst), "l"(src) : "memory");
}
__device__ __forceinline__ void cp_commit() {
    asm volatile("cp.async.commit_group;" ::: "memory");
}
template <int N>
__device__ __forceinline__ void cp_wait() {
    asm volatile("cp.async.wait_group %0;" :: "n"(N) : "memory");
}
__device__ __forceinline__ void lds128(uint32_t (&r)[4], uint32_t addr) {
    asm volatile("ld.shared.v4.u32 {%0,%1,%2,%3}, [%4];"
                 : "=r"(r[0]), "=r"(r[1]), "=r"(r[2]), "=r"(r[3]) : "r"(addr));
}
__device__ __forceinline__ void mma_f16(float (&d)[4], const uint32_t (&a)[4],
                                        uint32_t b0, uint32_t b1) {
    asm volatile(
        "mma.sync.aligned.m16n8k16.row.col.f32.f16.f16.f32 "
        "{%0,%1,%2,%3}, {%4,%5,%6,%7}, {%8,%9}, {%0,%1,%2,%3};"
        : "+f"(d[0]), "+f"(d[1]), "+f"(d[2]), "+f"(d[3])
        : "r"(a[0]), "r"(a[1]), "r"(a[2]), "r"(a[3]), "r"(b0), "r"(b1));
}
// streaming (evict-first) float4 load / float2 store
__device__ __forceinline__ float4 ldcs4(const float4* p) {
    float4 v;
    asm volatile("ld.global.cs.v4.f32 {%0,%1,%2,%3}, [%4];"
                 : "=f"(v.x), "=f"(v.y), "=f"(v.z), "=f"(v.w) : "l"(p));
    return v;
}
__device__ __forceinline__ void stcs2(float2* p, float a, float b) {
    asm volatile("st.global.cs.v2.f32 [%0], {%1,%2};"
                 :: "l"(p), "f"(a), "f"(b) : "memory");
}

// ------------------------------------------------------------------ prepass
// One kernel: blocks [0, MT*KCH) compact x into A-frag order; blocks
// [MT*KCH, MT*KCH + NT*KCH) compact w into B-frag order. Mask is column-global.
__global__ void __launch_bounds__(256) compact_kernel(const float4* __restrict__ x4,
                                                      const float4* __restrict__ w4,
                                                      const float4* __restrict__ mask4) {
    __shared__ uint32_t hsw[128 * HSTRIDE];
    __shared__ int s_j0[32], s_j1[32];

    const int b = blockIdx.x;
    const bool isx = (b < MT * KCH);
    const int bb = isx ? b : (b - MT * KCH);
    const int kc = bb & (KCH - 1);
    const int tile = bb >> 3;
    const float4* __restrict__ src = isx ? x4 : w4;
    const int tid = threadIdx.x;

    if (tid < 32) {
        float4 m = mask4[kc * 32 + tid];
        float mv[4] = {m.x, m.y, m.z, m.w};
        int j0 = -1, j1 = -1;
        #pragma unroll
        for (int j = 3; j >= 0; j--)
            if (mv[j] != 0.0f) { j1 = j0; j0 = j; }
        s_j0[tid] = j0;
        s_j1[tid] = j1;
    }
    __syncthreads();

    // phase 1: coalesced streaming float4 reads (read-once), batched x8 for MLP
    #pragma unroll
    for (int h = 0; h < 2; h++) {
        float4 f[8];
        #pragma unroll
        for (int j = 0; j < 8; j++) {
            int idx = tid + 256 * (h * 8 + j);
            int row = idx >> 5, gl = idx & 31;
            f[j] = ldcs4(&src[(size_t)(tile * 128 + row) * (DIN / 4) + kc * 32 + gl]);
        }
        #pragma unroll
        for (int j = 0; j < 8; j++) {
            int idx = tid + 256 * (h * 8 + j);
            int row = idx >> 5, gl = idx & 31;
            int j0 = s_j0[gl], j1 = s_j1[gl];
            float v0 = (j0 == 0) ? f[j].x : (j0 == 1) ? f[j].y : (j0 == 2) ? f[j].z : f[j].w;
            float v1 = (j1 == 0) ? f[j].x : (j1 == 1) ? f[j].y : (j1 == 2) ? f[j].z : f[j].w;
            if (j0 < 0) v0 = 0.0f;
            if (j1 < 0) v1 = 0.0f;
            hsw[row * HSTRIDE + gl] = h2bits(v0, v1);
        }
    }
    __syncthreads();

    if (isx) {
        unsigned char* dst = g_xc + ((size_t)(tile * KCH + kc)) * A_STAGE_BYTES;
        #pragma unroll
        for (int j = 0; j < 4; j++) {
            int o = tid + 256 * j;
            int l = o & 31, fi = o >> 5;
            int ks = fi & 3, mtl = fi >> 2;
            int r = mtl * 16 + (l >> 2);
            int wb = ks * 8 + (l & 3);
            uint4 v;
            v.x = hsw[r * HSTRIDE + wb];
            v.y = hsw[(r + 8) * HSTRIDE + wb];
            v.z = hsw[r * HSTRIDE + wb + 4];
            v.w = hsw[(r + 8) * HSTRIDE + wb + 4];
            *reinterpret_cast<uint4*>(dst + o * 16) = v;
        }
    } else {
        unsigned char* dst = g_wc + ((size_t)(tile * KCH + kc)) * B_STAGE_BYTES;
        #pragma unroll
        for (int j = 0; j < 4; j++) {
            int o = tid + 256 * j;
            int l = o & 31, fj = o >> 5;
            int ks = fj & 3, p = fj >> 2;
            int n = p * 16 + (l >> 2);
            int pr = ks * 8 + (l & 3);
            uint4 v;
            v.x = hsw[n * HSTRIDE + pr];
            v.y = hsw[n * HSTRIDE + pr + 4];
            v.z = hsw[(n + 8) * HSTRIDE + pr];
            v.w = hsw[(n + 8) * HSTRIDE + pr + 4];
            *reinterpret_cast<uint4*>(dst + o * 16) = v;
        }
    }

    // PDL: allow the GEMM grid to begin launching once all compact blocks
    // reach here. Memory visibility is enforced by the consumer's
    // cudaGridDependencySynchronize(), not by this trigger.
    cudaTriggerProgrammaticLaunchCompletion();
}

// ------------------------------------------------------------------ GEMM
// R8 configuration (DO NOT TOUCH): 3 stages x (16KB A + 16KB B) = 96KB,
// 2 CTAs/SM, in-register fragment double buffering, one __syncthreads/chunk.
#define SMEM_BYTES (STAGES * (A_STAGE_BYTES + B_STAGE_BYTES))   // 98304

__global__ void __launch_bounds__(THREADS, 2) gemm_kernel(float* __restrict__ out) {
    extern __shared__ char smem[];
    const uint32_t sA0 = smem_u32(smem);
    const uint32_t sB0 = sA0 + STAGES * A_STAGE_BYTES;

    const int tid = threadIdx.x;
    const int wid = tid >> 5, lid = tid & 31;
    const int nt = blockIdx.x, mt = blockIdx.y;
    const int wm = wid & 1;         // 2 m-warps (64 rows)
    const int wn = wid >> 1;        // 2 n-warps (64 cols = 4 pairs)

    const unsigned char* gA = g_xc + ((size_t)mt * KCH) * A_STAGE_BYTES;
    const unsigned char* gB = g_wc + ((size_t)nt * KCH) * B_STAGE_BYTES;

    auto load_stage = [&](int s, int c) {
        uint32_t dA = sA0 + s * A_STAGE_BYTES + tid * 16;
        const unsigned char* srcA = gA + (size_t)c * A_STAGE_BYTES + tid * 16;
        #pragma unroll
        for (int j = 0; j < 8; j++) cp16(dA + j * 2048, srcA + j * 2048);
        uint32_t dB = sB0 + s * B_STAGE_BYTES + tid * 16;
        const unsigned char* srcB = gB + (size_t)c * B_STAGE_BYTES + tid * 16;
        #pragma unroll
        for (int j = 0; j < 8; j++) cp16(dB + j * 2048, srcB + j * 2048);
    };

    float acc[4][8][4];
    #pragma unroll
    for (int i = 0; i < 4; i++)
        #pragma unroll
        for (int j = 0; j < 8; j++)
            #pragma unroll
            for (int v = 0; v < 4; v++) acc[i][j][v] = 0.0f;

    // PDL: this grid launched during the compact kernel's tail. Wait here for
    // full producer-grid completion + memory visibility before reading g_xc/g_wc.
    cudaGridDependencySynchronize();

    uint32_t ab[2][4][4], bb[2][4][4];
    auto ldfrags = [&](int buf, int s, int ks) {
        const uint32_t aB = sA0 + s * A_STAGE_BYTES + ((wm * 4) * 4 + ks) * 512 + lid * 16;
        #pragma unroll
        for (int i = 0; i < 4; i++) lds128(ab[buf][i], aB + i * 2048);
        const uint32_t bB = sB0 + s * B_STAGE_BYTES + ((wn * 4) * 4 + ks) * 512 + lid * 16;
        #pragma unroll
        for (int p = 0; p < 4; p++) lds128(bb[buf][p], bB + p * 2048);
    };
    auto domma = [&](int buf) {
        #pragma unroll
        for (int i = 0; i < 4; i++)
            #pragma unroll
            for (int p = 0; p < 4; p++) {
                mma_f16(acc[i][2 * p],     ab[buf][i], bb[buf][p][0], bb[buf][p][1]);
                mma_f16(acc[i][2 * p + 1], ab[buf][i], bb[buf][p][2], bb[buf][p][3]);
            }
    };

    // prologue: fill stages 0,1; load ks0 frags of chunk 0
    load_stage(0, 0); cp_commit();
    load_stage(1, 1); cp_commit();
    cp_wait<1>();
    __syncthreads();
    ldfrags(0, 0, 0);

    int s = 0;
    for (int c = 0; c < KCH; c++) {
        const int snext = (s == STAGES - 1) ? 0 : s + 1;
        const int sload = (snext == STAGES - 1) ? 0 : snext + 1;
        if (c + 2 < KCH) load_stage(sload, c + 2);
        cp_commit();

        ldfrags(1, s, 1); domma(0);     // ks0 compute, ks1 prefetch
        ldfrags(0, s, 2); domma(1);     // ks1
        ldfrags(1, s, 3); domma(0);     // ks2
        cp_wait<1>();                   // chunk c+1 resident (c+2 may pend)
        __syncthreads();                // stage s fully read CTA-wide
        if (c + 1 < KCH) ldfrags(0, snext, 0);
        domma(1);                       // ks3
        s = snext;
    }

    // epilogue: streaming stores (output is never re-read; keep L2 for g_xc)
    const int rowW = mt * BM + wm * 64 + (lid >> 2);
    const int colW = nt * BN + wn * 64 + (lid & 3) * 2;
    #pragma unroll
    for (int i = 0; i < 4; i++) {
        const size_t r0 = (size_t)(rowW + i * 16) * DOUT;
        const size_t r1 = r0 + (size_t)8 * DOUT;
        #pragma unroll
        for (int j = 0; j < 8; j++) {
            const int cc = colW + j * 8;
            stcs2(reinterpret_cast<float2*>(out + r0 + cc), acc[i][j][0], acc[i][j][1]);
            stcs2(reinterpret_cast<float2*>(out + r1 + cc), acc[i][j][2], acc[i][j][3]);
        }
    }
}

// ------------------------------------------------------------------ launch
extern "C" void kernel_launch(void* const* d_in, const int* in_sizes, int n_in,
                              void* d_out, int out_size) {
    const float* x    = (const float*)d_in[0];
    const float* w    = (const float*)d_in[1];
    const float* mask = (const float*)d_in[2];
    float* out        = (float*)d_out;

    cudaFuncSetAttribute(gemm_kernel,
                         cudaFuncAttributeMaxDynamicSharedMemorySize, SMEM_BYTES);

    compact_kernel<<<MT * KCH + NT * KCH, 256>>>((const float4*)x, (const float4*)w,
                                                 (const float4*)mask);

    // GEMM with programmatic dependent launch: begins launching during the
    // compact kernel's tail; correctness held by cudaGridDependencySynchronize.
    cudaLaunchConfig_t cfg = {};
    cfg.gridDim = dim3(NT, MT);
    cfg.blockDim = dim3(THREADS);
    cfg.dynamicSmemBytes = SMEM_BYTES;
    cfg.stream = 0;
    cudaLaunchAttribute attr[1];
    attr[0].id = cudaLaunchAttributeProgrammaticStreamSerialization;
    attr[0].val.programmaticStreamSerializationAllowed = 1;
    cfg.attrs = attr;
    cfg.numAttrs = 1;
    cudaLaunchKernelEx(&cfg, gemm_kernel, out);
}